// round 11
// baseline (speedup 1.0000x reference)
#include <cuda_runtime.h>
#include <cuda_fp16.h>
#include <cstdint>

#define NB 4
#define NT 4096
#define NC 1024
#define NH 16
#define ND 64
#define NM (NB*NT)          // 16384 rows
#define KVSPL 8

// ---------------------------------------------------------------------------
// Device global scratch (allocation-free requirement)
// g_Q/g_K/g_V are HEAD-MAJOR: [b][h][t][64] (contiguous per head)
// ---------------------------------------------------------------------------
__device__ __half g_x16[(size_t)NM*NC];
__device__ __half g_y16[(size_t)NM*NC];
__device__ __half g_a16[(size_t)NM*NC];
__device__ __half g_wq[NC*NC];
__device__ __half g_wk[NC*NC];
__device__ __half g_wv[NC*NC];
__device__ __half g_wp[NC*NC];
__device__ __half g_Q[(size_t)NM*NC];
__device__ __half g_K[(size_t)NM*NC];
__device__ __half g_V[(size_t)NM*NC];
__device__ float g_KV2[KVSPL*64*64*64];   // [split][bh][d][e]
__device__ float g_KS2[KVSPL*64*64];      // [split][bh][d]
__device__ __half g_KVT[(size_t)64*5760]; // [bh][80 rows x 72 halfs]: rows 0-63 kv^T[e][d], row 64 ksum

// ---------------------------------------------------------------------------
// PTX helpers (sm_80+ portable: cp.async / ldmatrix / mma.sync)
// ---------------------------------------------------------------------------
__device__ __forceinline__ uint32_t smem_to_u32(const void* p) {
    uint32_t a;
    asm("{ .reg .u64 t; cvta.to.shared.u64 t, %1; cvt.u32.u64 %0, t; }" : "=r"(a) : "l"(p));
    return a;
}
__device__ __forceinline__ void cp16(uint32_t s, const void* g) {
    asm volatile("cp.async.cg.shared.global [%0], [%1], 16;" :: "r"(s), "l"(g));
}
__device__ __forceinline__ void cp_commit() { asm volatile("cp.async.commit_group;" ::: "memory"); }
template<int N> __device__ __forceinline__ void cp_wait() {
    asm volatile("cp.async.wait_group %0;" :: "n"(N) : "memory");
}
__device__ __forceinline__ void ldm_x4(uint32_t addr, uint32_t* r) {
    asm volatile("ldmatrix.sync.aligned.m8n8.x4.shared.b16 {%0,%1,%2,%3}, [%4];"
                 : "=r"(r[0]), "=r"(r[1]), "=r"(r[2]), "=r"(r[3]) : "r"(addr));
}
__device__ __forceinline__ void ldm_x4_t(uint32_t addr, uint32_t* r) {
    asm volatile("ldmatrix.sync.aligned.m8n8.x4.trans.shared.b16 {%0,%1,%2,%3}, [%4];"
                 : "=r"(r[0]), "=r"(r[1]), "=r"(r[2]), "=r"(r[3]) : "r"(addr));
}
__device__ __forceinline__ void mma_f16(float* d, const uint32_t* a, const uint32_t* b) {
    asm volatile("mma.sync.aligned.m16n8k16.row.col.f32.f16.f16.f32 "
                 "{%0,%1,%2,%3}, {%4,%5,%6,%7}, {%8,%9}, {%0,%1,%2,%3};"
                 : "+f"(d[0]), "+f"(d[1]), "+f"(d[2]), "+f"(d[3])
                 : "r"(a[0]), "r"(a[1]), "r"(a[2]), "r"(a[3]), "r"(b[0]), "r"(b[1]));
}

// softmax over 64 cols: 16 values per lane + quad reduction (xor 1, 2)
__device__ __forceinline__ void softmax16(float* v) {
    float mx = v[0];
    #pragma unroll
    for (int j = 1; j < 16; j++) mx = fmaxf(mx, v[j]);
    mx = fmaxf(mx, __shfl_xor_sync(0xffffffffu, mx, 1));
    mx = fmaxf(mx, __shfl_xor_sync(0xffffffffu, mx, 2));
    float s = 0.f;
    #pragma unroll
    for (int j = 0; j < 16; j++) { v[j] = __expf(v[j] - mx); s += v[j]; }
    s += __shfl_xor_sync(0xffffffffu, s, 1);
    s += __shfl_xor_sync(0xffffffffu, s, 2);
    float inv = 1.f / s;
    #pragma unroll
    for (int j = 0; j < 16; j++) v[j] *= inv;
}

// ---------------------------------------------------------------------------
// fp16 GEMM: Out[m,n] = sum_k A[m,k]*W[n,k] + bias[n], opt. softmax per 64.
// CTA 128(M) x 128(N), BK=32, 5-stage cp.async pipeline; 8 warps as 4(M)x2(N)
// with 32x64 warp tiles; 2 CTAs/SM. One __syncthreads per kt.
// head_major: fp16 output written as [b][h][t][64] (warp N-tile == one head).
// ---------------------------------------------------------------------------
#define BM 128
#define BN 128
#define BK 32
#define STAGES 5
#define NKT (NC/BK)                // 32
#define SROW 40                    // padded row length in halfwords
#define AMAT (128*SROW*2)          // 10240
#define OFF_B AMAT
#define STG_BYTES (2*AMAT)         // 20480
#define GSMEM (STAGES*STG_BYTES)   // 102400

__device__ __forceinline__ void gemm_body(
    const __half* __restrict__ A16, const __half* __restrict__ B16,
    const float* __restrict__ bias, float* __restrict__ OutF,
    __half* __restrict__ OutH, int do_softmax, int head_major)
{
    extern __shared__ __align__(128) char sm[];
    uint32_t smb = smem_to_u32(sm);
    const int tid = threadIdx.x;
    const int m0 = blockIdx.y * BM, n0 = blockIdx.x * BN;

    const __half* a_g = A16 + (size_t)m0 * NC;
    const __half* b_g = B16 + (size_t)n0 * NC;

    auto issue = [&](int stage, int k0) {
        uint32_t sb = smb + stage * STG_BYTES;
        #pragma unroll
        for (int i = 0; i < 2; i++) {                 // A and B: 512 cp16 each
            int g = i * 256 + tid;
            int row = g >> 2, c = g & 3;
            uint32_t so = row * (SROW * 2) + c * 16;
            size_t  go = (size_t)row * NC + k0 + c * 8;
            cp16(sb + so,         a_g + go);
            cp16(sb + OFF_B + so, b_g + go);
        }
    };

    #pragma unroll
    for (int s = 0; s < STAGES - 1; s++) { issue(s, s * BK); cp_commit(); }

    const int wid = tid >> 5, lane = tid & 31;
    const int wm = wid & 3, wn = wid >> 2;            // warp tile: 32(M) x 64(N)

    float acc[2][8][4];
    #pragma unroll
    for (int a = 0; a < 2; a++)
        #pragma unroll
        for (int b = 0; b < 8; b++)
            #pragma unroll
            for (int c = 0; c < 4; c++) acc[a][b][c] = 0.f;

    const int a_row = wm * 32 + (lane & 7) + ((lane >> 3) & 1) * 8;   // + mt*16
    const int b_row = wn * 64 + (lane & 15);                           // + p*16
    const int colb  = (lane >> 4) * 16;                                // + ks*32

    for (int kt = 0; kt < NKT; kt++) {
        cp_wait<STAGES - 2>();
        __syncthreads();
        if (kt + STAGES - 1 < NKT) issue((kt + STAGES - 1) % STAGES, (kt + STAGES - 1) * BK);
        cp_commit();
        uint32_t sb = smb + (kt % STAGES) * STG_BYTES;
        #pragma unroll
        for (int ks = 0; ks < 2; ks++) {
            uint32_t ah[2][4];
            #pragma unroll
            for (int mt = 0; mt < 2; mt++)
                ldm_x4(sb + (a_row + mt * 16) * (SROW * 2) + ks * 32 + colb, ah[mt]);
            uint32_t bh[8][2];
            #pragma unroll
            for (int p = 0; p < 4; p++) {
                uint32_t t[4];
                ldm_x4(sb + OFF_B + (b_row + p * 16) * (SROW * 2) + ks * 32 + colb, t);
                bh[2*p][0] = t[0]; bh[2*p+1][0] = t[1]; bh[2*p][1] = t[2]; bh[2*p+1][1] = t[3];
            }
            #pragma unroll
            for (int mt = 0; mt < 2; mt++)
                #pragma unroll
                for (int nt = 0; nt < 8; nt++) mma_f16(acc[mt][nt], ah[mt], bh[nt]);
        }
    }

    // ---- Epilogue: bias (+softmax per 64-wide head) + store ----
    float2 bias2[8];
    const int cb = n0 + wn * 64 + (lane & 3) * 2;
    #pragma unroll
    for (int nt = 0; nt < 8; nt++)
        bias2[nt] = *reinterpret_cast<const float2*>(&bias[cb + nt * 8]);

    const int hh = (n0 + wn * 64) >> 6;               // head (head_major path)
    #pragma unroll
    for (int mt = 0; mt < 2; mt++) {
        float va[16], vb[16];
        #pragma unroll
        for (int nt = 0; nt < 8; nt++) {
            va[2*nt]   = acc[mt][nt][0] + bias2[nt].x;
            va[2*nt+1] = acc[mt][nt][1] + bias2[nt].y;
            vb[2*nt]   = acc[mt][nt][2] + bias2[nt].x;
            vb[2*nt+1] = acc[mt][nt][3] + bias2[nt].y;
        }
        if (do_softmax) { softmax16(va); softmax16(vb); }
        const int rowa = m0 + wm * 32 + mt * 16 + (lane >> 2);
        const int rowb = rowa + 8;
        if (OutH) {
            if (head_major) {
                int ba = rowa >> 12, ta = rowa & (NT - 1);
                size_t base = ((size_t)(ba * NH + hh) * NT + ta) * ND + (lane & 3) * 2;
                #pragma unroll
                for (int nt = 0; nt < 8; nt++) {
                    *reinterpret_cast<__half2*>(&OutH[base + nt * 8]) =
                        __floats2half2_rn(va[2*nt], va[2*nt+1]);
                    *reinterpret_cast<__half2*>(&OutH[base + 8 * ND + nt * 8]) =
                        __floats2half2_rn(vb[2*nt], vb[2*nt+1]);
                }
            } else {
                #pragma unroll
                for (int nt = 0; nt < 8; nt++) {
                    *reinterpret_cast<__half2*>(&OutH[(size_t)rowa * NC + cb + nt * 8]) =
                        __floats2half2_rn(va[2*nt], va[2*nt+1]);
                    *reinterpret_cast<__half2*>(&OutH[(size_t)rowb * NC + cb + nt * 8]) =
                        __floats2half2_rn(vb[2*nt], vb[2*nt+1]);
                }
            }
        } else {
            #pragma unroll
            for (int nt = 0; nt < 8; nt++) {
                *reinterpret_cast<float2*>(&OutF[(size_t)rowa * NC + cb + nt * 8]) =
                    make_float2(va[2*nt], va[2*nt+1]);
                *reinterpret_cast<float2*>(&OutF[(size_t)rowb * NC + cb + nt * 8]) =
                    make_float2(vb[2*nt], vb[2*nt+1]);
            }
        }
    }
}

__global__ __launch_bounds__(256, 2) void qkv_gemm(
    const float* __restrict__ bq, const float* __restrict__ bk, const float* __restrict__ bv)
{
    int z = blockIdx.z;
    if (z == 0)      gemm_body(g_x16, g_wq, bq, nullptr, g_Q, 1, 1);
    else if (z == 1) gemm_body(g_y16, g_wk, bk, nullptr, g_K, 1, 1);
    else             gemm_body(g_y16, g_wv, bv, nullptr, g_V, 0, 1);
}

__global__ __launch_bounds__(256, 2) void proj_gemm(
    const float* __restrict__ bp, float* __restrict__ out)
{
    gemm_body(g_a16, g_wp, bp, out, nullptr, 0, 0);
}

// ---------------------------------------------------------------------------
// fp32 -> fp16 converts (merged launches)
// ---------------------------------------------------------------------------
__global__ __launch_bounds__(256) void convert_act(const float* __restrict__ x,
                                                   const float* __restrict__ y)
{
    const float* src = blockIdx.y ? y : x;
    __half* dh = blockIdx.y ? g_y16 : g_x16;
    int g = blockIdx.x * 256 + threadIdx.x;
    const float4* p = reinterpret_cast<const float4*>(src) + (size_t)g * 2;
    float4 a = p[0], b = p[1];
    alignas(16) __half h[8] = {
        __float2half_rn(a.x), __float2half_rn(a.y), __float2half_rn(a.z), __float2half_rn(a.w),
        __float2half_rn(b.x), __float2half_rn(b.y), __float2half_rn(b.z), __float2half_rn(b.w) };
    *reinterpret_cast<uint4*>(dh + (size_t)g * 8) = *reinterpret_cast<uint4*>(h);
}

__global__ __launch_bounds__(256) void convert_w(const float* __restrict__ wq,
                                                 const float* __restrict__ wk,
                                                 const float* __restrict__ wv,
                                                 const float* __restrict__ wp)
{
    const float* src; __half* dh;
    switch (blockIdx.y) {
        case 0: src = wq; dh = g_wq; break;
        case 1: src = wk; dh = g_wk; break;
        case 2: src = wv; dh = g_wv; break;
        default: src = wp; dh = g_wp; break;
    }
    int g = blockIdx.x * 256 + threadIdx.x;
    const float4* p = reinterpret_cast<const float4*>(src) + (size_t)g * 2;
    float4 a = p[0], b = p[1];
    alignas(16) __half h[8] = {
        __float2half_rn(a.x), __float2half_rn(a.y), __float2half_rn(a.z), __float2half_rn(a.w),
        __float2half_rn(b.x), __float2half_rn(b.y), __float2half_rn(b.z), __float2half_rn(b.w) };
    *reinterpret_cast<uint4*>(dh + (size_t)g * 8) = *reinterpret_cast<uint4*>(h);
}

// ---------------------------------------------------------------------------
// kv via HMMA: kv[d][e] = sum_n K[n,d]*V[n,e]; ksum[d] = sum_n K[n,d]
// grid (64 bh, KVSPL splits), 256 thr (8 warps as 4(d) x 2(e)).
// K/V head-major -> 16KB contiguous tile loads.
// ---------------------------------------------------------------------------
#define KV_ROW 176                 // bytes per smem row (88 halfs)
#define KV_MAT (128*KV_ROW)        // 22528
#define KV_STG (2*KV_MAT)          // 45056 (K then V)
#define KV_SMEM (2*KV_STG)         // 90112
#define KV_TILES (NT/KVSPL/128)    // 4

__global__ __launch_bounds__(256, 1) void kv_hmma()
{
    extern __shared__ __align__(128) char sm[];
    uint32_t smb = smem_to_u32(sm);
    const int bh = blockIdx.x, split = blockIdx.y;
    const int tid = threadIdx.x, wid = tid >> 5, lane = tid & 31;
    const int wm = wid & 3, wn = wid >> 2;
    const int m0 = wm * 16, n0 = wn * 32;
    const int lr = lane & 7, lg = lane >> 3;

    const __half* Kp = g_K + (size_t)bh * NT * ND;
    const __half* Vp = g_V + (size_t)bh * NT * ND;
    const int tokbase = split * (NT / KVSPL);

    auto issue = [&](int stage, int tile) {
        uint32_t sb = smb + stage * KV_STG;
        int t0 = tokbase + tile * 128;
        #pragma unroll
        for (int i = 0; i < 4; i++) {
            int slot = i * 256 + tid;
            int row = slot >> 3, c = slot & 7;
            cp16(sb + row * KV_ROW + c * 16,          Kp + (size_t)(t0 + row) * ND + c * 8);
            cp16(sb + KV_MAT + row * KV_ROW + c * 16, Vp + (size_t)(t0 + row) * ND + c * 8);
        }
        int row = tid >> 1, which = tid & 1;
        uint4 padv = which ? make_uint4(0u, 0u, 0u, 0u)
                           : make_uint4(0x00003C00u, 0u, 0u, 0u);
        *reinterpret_cast<uint4*>(sm + stage * KV_STG + KV_MAT + row * KV_ROW + 128 + which * 16) = padv;
    };

    float acc[4][4] = {};
    float accS[4]   = {};

    issue(0, 0); cp_commit();

    for (int tile = 0; tile < KV_TILES; tile++) {
        if (tile + 1 < KV_TILES) { issue((tile + 1) & 1, tile + 1); cp_commit(); cp_wait<1>(); }
        else cp_wait<0>();
        __syncthreads();
        uint32_t kb = smb + (tile & 1) * KV_STG;
        uint32_t vb = kb + KV_MAT;
        #pragma unroll
        for (int s = 0; s < 8; s++) {
            int ts = s * 16;
            uint32_t a[4];
            ldm_x4_t(kb + (ts + lr + (lg >> 1) * 8) * KV_ROW + (m0 + (lg & 1) * 8) * 2, a);
            #pragma unroll
            for (int eg = 0; eg < 2; eg++) {
                uint32_t t[4];
                ldm_x4_t(vb + (ts + lr + (lg & 1) * 8) * KV_ROW + (n0 + eg * 16 + (lg >> 1) * 8) * 2, t);
                mma_f16(acc[eg * 2 + 0], a, t + 0);
                mma_f16(acc[eg * 2 + 1], a, t + 2);
            }
            if (wn == 1) {
                uint32_t t[4];
                ldm_x4_t(vb + (ts + lr + (lg & 1) * 8) * KV_ROW + (64 + (lg >> 1) * 8) * 2, t);
                mma_f16(accS, a, t + 0);
            }
        }
        __syncthreads();
    }

    float* kvout = g_KV2 + ((size_t)split * 64 + bh) * 4096;
    const int r0 = m0 + (lane >> 2), c0 = (lane & 3) * 2;
    #pragma unroll
    for (int j = 0; j < 4; j++) {
        *reinterpret_cast<float2*>(&kvout[r0 * 64 + n0 + j * 8 + c0]) =
            make_float2(acc[j][0], acc[j][1]);
        *reinterpret_cast<float2*>(&kvout[(r0 + 8) * 64 + n0 + j * 8 + c0]) =
            make_float2(acc[j][2], acc[j][3]);
    }
    if (wn == 1 && (lane & 3) == 0) {
        float* ksout = g_KS2 + ((size_t)split * 64 + bh) * 64;
        ksout[m0 + (lane >> 2)]     = accS[0];
        ksout[m0 + 8 + (lane >> 2)] = accS[2];
    }
}

// ---------------------------------------------------------------------------
// kv_reduce: sum KVSPL splits -> fp16 kv^T tile [80 rows x 72 halfs] per bh:
//   rows 0-63: kvT[e][d] = kv[d][e]; row 64: ksum[d]; rows 65-71: zero.
// ---------------------------------------------------------------------------
__global__ __launch_bounds__(256) void kv_reduce()
{
    const int bh = blockIdx.x, tid = threadIdx.x;
    __half* dst = g_KVT + (size_t)bh * 5760;
    #pragma unroll
    for (int i = 0; i < 16; i++) {
        int idx = i * 256 + tid;
        int d = idx >> 6, e = idx & 63;
        float s = 0.f;
        #pragma unroll
        for (int sp = 0; sp < KVSPL; sp++)
            s += g_KV2[((size_t)sp * 64 + bh) * 4096 + idx];
        dst[e * 72 + d] = __float2half_rn(s);
    }
    if (tid < 64) {
        float s = 0.f;
        #pragma unroll
        for (int sp = 0; sp < KVSPL; sp++) s += g_KS2[(sp * 64 + bh) * 64 + tid];
        dst[64 * 72 + tid] = __float2half_rn(s);
    }
    // zero row 64 cols 64-71 and rows 65-71 (8 + 504 halfs)
    for (int j = tid; j < 512; j += 256) dst[64 * 72 + 64 + j] = __float2half_rn(0.f);
}

// ---------------------------------------------------------------------------
// attn via HMMA: os[t,e] = sum_d q[t,d]*kvT[e,d]; ds[t] from ksum row (n=64).
// out[t,e] = q[t,e] + os/ds -> fp16 token-major for proj GEMM.
// Q head-major -> contiguous 16KB tile loads.
// ---------------------------------------------------------------------------
#define AT_ROW 144   // 72 halfs per smem row

__global__ __launch_bounds__(256) void attn_hmma()
{
    __shared__ __align__(16) char sq[128 * AT_ROW];  // Q tile: 128 tok x 64 d
    __shared__ __align__(16) char sb[80 * AT_ROW];   // kvT + ksum tile
    const int bh = blockIdx.y, b = bh / NH, h = bh % NH;
    const int t0 = blockIdx.x * 128;
    const int tid = threadIdx.x, wid = tid >> 5, lane = tid & 31;
    uint32_t sqb = smem_to_u32(sq), sbb = smem_to_u32(sb);

    const __half* Qp = g_Q + ((size_t)bh * NT + t0) * ND;
    #pragma unroll
    for (int i = 0; i < 4; i++) {                     // 1024 cp16
        int slot = i * 256 + tid;
        int row = slot >> 3, c = slot & 7;
        cp16(sqb + row * AT_ROW + c * 16, Qp + (size_t)row * ND + c * 8);
    }
    const __half* Bp = g_KVT + (size_t)bh * 5760;     // 720 cp16
    for (int s = tid; s < 720; s += 256) cp16(sbb + s * 16, Bp + s * 8);
    cp_commit(); cp_wait<0>();
    __syncthreads();

    float acc[9][4] = {};                              // 8 n-tiles + ksum tile
    const int a_row = wid * 16 + (lane & 7) + ((lane >> 3) & 1) * 8;
    const int b_row = lane & 15;
    const int colb  = (lane >> 4) * 16;

    #pragma unroll
    for (int ks = 0; ks < 4; ks++) {
        uint32_t a[4];
        ldm_x4(sqb + a_row * AT_ROW + ks * 32 + colb, a);
        #pragma unroll
        for (int p = 0; p < 5; p++) {
            uint32_t t[4];
            ldm_x4(sbb + (b_row + p * 16) * AT_ROW + ks * 32 + colb, t);
            uint32_t f0[2] = { t[0], t[2] };
            mma_f16(acc[2 * p], a, f0);
            if (p < 4) {
                uint32_t f1[2] = { t[1], t[3] };
                mma_f16(acc[2 * p + 1], a, f1);
            }
        }
    }

    // ds broadcast: n=64 column lives in lane&3==0, regs 0 (row r) / 2 (row r+8)
    float ds0 = __shfl_sync(0xffffffffu, acc[8][0], lane & ~3);
    float ds1 = __shfl_sync(0xffffffffu, acc[8][2], lane & ~3);
    ds0 = 1.f / ds0; ds1 = 1.f / ds1;

    const int r = wid * 16 + (lane >> 2);
    const int cb = (lane & 3) * 2;
    __half* outp = g_a16 + ((size_t)b * NT + t0) * NC + h * ND;
    #pragma unroll
    for (int nt = 0; nt < 8; nt++) {
        int e = nt * 8 + cb;
        __half2 q0 = *reinterpret_cast<const __half2*>(sq + r * AT_ROW + e * 2);
        __half2 q1 = *reinterpret_cast<const __half2*>(sq + (r + 8) * AT_ROW + e * 2);
        float2 qf0 = __half22float2(q0), qf1 = __half22float2(q1);
        *reinterpret_cast<__half2*>(outp + (size_t)r * NC + e) =
            __floats2half2_rn(qf0.x + acc[nt][0] * ds0, qf0.y + acc[nt][1] * ds0);
        *reinterpret_cast<__half2*>(outp + (size_t)(r + 8) * NC + e) =
            __floats2half2_rn(qf1.x + acc[nt][2] * ds1, qf1.y + acc[nt][3] * ds1);
    }
}

// ---------------------------------------------------------------------------
extern "C" void kernel_launch(void* const* d_in, const int* in_sizes, int n_in,
                              void* d_out, int out_size)
{
    const float* x  = (const float*)d_in[0];
    const float* y  = (const float*)d_in[1];
    const float* Wq = (const float*)d_in[2];
    const float* bq = (const float*)d_in[3];
    const float* Wk = (const float*)d_in[4];
    const float* bk = (const float*)d_in[5];
    const float* Wv = (const float*)d_in[6];
    const float* bv = (const float*)d_in[7];
    const float* Wp = (const float*)d_in[8];
    const float* bp = (const float*)d_in[9];
    float* out = (float*)d_out;
    (void)in_sizes; (void)n_in; (void)out_size;

    cudaFuncSetAttribute(qkv_gemm,  cudaFuncAttributeMaxDynamicSharedMemorySize, GSMEM);
    cudaFuncSetAttribute(proj_gemm, cudaFuncAttributeMaxDynamicSharedMemorySize, GSMEM);
    cudaFuncSetAttribute(kv_hmma,   cudaFuncAttributeMaxDynamicSharedMemorySize, KV_SMEM);

    // 1. fp32 -> fp16 (merged)
    convert_act<<<dim3(NM * NC / 8 / 256, 2), 256>>>(x, y);
    convert_w<<<dim3(NC * NC / 8 / 256, 4), 256>>>(Wq, Wk, Wv, Wp);

    // 2. Q/K/V projections (softmax fused for Q,K) -> fp16 head-major
    qkv_gemm<<<dim3(NC / BN, NM / BM, 3), 256, GSMEM>>>(bq, bk, bv);

    // 3. kv = K^T V (+ksum) on tensor cores, 8-way T split, then fp16 reduce
    kv_hmma<<<dim3(NB * NH, KVSPL), 256, KV_SMEM>>>();
    kv_reduce<<<NB * NH, 256>>>();

    // 4. linear-attention combine on tensor cores -> fp16 for proj GEMM
    attn_hmma<<<dim3(NT / 128, NB * NH), 256>>>();

    // 5. output projection -> d_out (fp32)
    proj_gemm<<<dim3(NC / BN, NM / BM, 1), 256, GSMEM>>>(bp, out);
}

// round 12
// speedup vs baseline: 1.0059x; 1.0059x over previous
#include <cuda_runtime.h>
#include <cuda_fp16.h>
#include <cstdint>

#define NB 4
#define NT 4096
#define NC 1024
#define NH 16
#define ND 64
#define NM (NB*NT)          // 16384 rows
#define KVSPL 4

// ---------------------------------------------------------------------------
// Device global scratch (allocation-free requirement). Q/K/V token-major.
// ---------------------------------------------------------------------------
__device__ __half g_x16[(size_t)NM*NC];
__device__ __half g_y16[(size_t)NM*NC];
__device__ __half g_a16[(size_t)NM*NC];
__device__ __half g_wq[NC*NC];
__device__ __half g_wk[NC*NC];
__device__ __half g_wv[NC*NC];
__device__ __half g_wp[NC*NC];
__device__ __half g_Q[(size_t)NM*NC];
__device__ __half g_K[(size_t)NM*NC];
__device__ __half g_V[(size_t)NM*NC];
__device__ float g_KV2[KVSPL*64*64*64];   // [split][bh][d][e]
__device__ float g_KS2[KVSPL*64*64];      // [split][bh][d]
__device__ __half g_KVT[(size_t)64*5760]; // [bh][80 rows x 72 halfs]: rows 0-63 kv^T[e][d], row 64 ksum

// ---------------------------------------------------------------------------
// PTX helpers (sm_80+ portable: cp.async / ldmatrix / mma.sync)
// ---------------------------------------------------------------------------
__device__ __forceinline__ uint32_t smem_to_u32(const void* p) {
    uint32_t a;
    asm("{ .reg .u64 t; cvta.to.shared.u64 t, %1; cvt.u32.u64 %0, t; }" : "=r"(a) : "l"(p));
    return a;
}
__device__ __forceinline__ void cp16(uint32_t s, const void* g) {
    asm volatile("cp.async.cg.shared.global [%0], [%1], 16;" :: "r"(s), "l"(g));
}
__device__ __forceinline__ void cp_commit() { asm volatile("cp.async.commit_group;" ::: "memory"); }
template<int N> __device__ __forceinline__ void cp_wait() {
    asm volatile("cp.async.wait_group %0;" :: "n"(N) : "memory");
}
__device__ __forceinline__ void ldm_x4(uint32_t addr, uint32_t* r) {
    asm volatile("ldmatrix.sync.aligned.m8n8.x4.shared.b16 {%0,%1,%2,%3}, [%4];"
                 : "=r"(r[0]), "=r"(r[1]), "=r"(r[2]), "=r"(r[3]) : "r"(addr));
}
__device__ __forceinline__ void ldm_x4_t(uint32_t addr, uint32_t* r) {
    asm volatile("ldmatrix.sync.aligned.m8n8.x4.trans.shared.b16 {%0,%1,%2,%3}, [%4];"
                 : "=r"(r[0]), "=r"(r[1]), "=r"(r[2]), "=r"(r[3]) : "r"(addr));
}
__device__ __forceinline__ void mma_f16(float* d, const uint32_t* a, const uint32_t* b) {
    asm volatile("mma.sync.aligned.m16n8k16.row.col.f32.f16.f16.f32 "
                 "{%0,%1,%2,%3}, {%4,%5,%6,%7}, {%8,%9}, {%0,%1,%2,%3};"
                 : "+f"(d[0]), "+f"(d[1]), "+f"(d[2]), "+f"(d[3])
                 : "r"(a[0]), "r"(a[1]), "r"(a[2]), "r"(a[3]), "r"(b[0]), "r"(b[1]));
}

// softmax over 64 cols: 16 values per lane + quad reduction (xor 1, 2)
__device__ __forceinline__ void softmax16(float* v) {
    float mx = v[0];
    #pragma unroll
    for (int j = 1; j < 16; j++) mx = fmaxf(mx, v[j]);
    mx = fmaxf(mx, __shfl_xor_sync(0xffffffffu, mx, 1));
    mx = fmaxf(mx, __shfl_xor_sync(0xffffffffu, mx, 2));
    float s = 0.f;
    #pragma unroll
    for (int j = 0; j < 16; j++) { v[j] = __expf(v[j] - mx); s += v[j]; }
    s += __shfl_xor_sync(0xffffffffu, s, 1);
    s += __shfl_xor_sync(0xffffffffu, s, 2);
    float inv = 1.f / s;
    #pragma unroll
    for (int j = 0; j < 16; j++) v[j] *= inv;
}

// ---------------------------------------------------------------------------
// fp16 GEMM: Out[m,n] = sum_k A[m,k]*W[n,k] + bias[n], opt. softmax per 64.
// CTA 128(M) x 128(N), BK=32, 5-stage cp.async pipeline; 8 warps as 4(M)x2(N)
// with 32x64 warp tiles; 2 CTAs/SM. One __syncthreads per kt.
// ---------------------------------------------------------------------------
#define BM 128
#define BN 128
#define BK 32
#define STAGES 5
#define NKT (NC/BK)                // 32
#define SROW 40                    // padded row length in halfwords
#define AMAT (128*SROW*2)          // 10240
#define OFF_B AMAT
#define STG_BYTES (2*AMAT)         // 20480
#define GSMEM (STAGES*STG_BYTES)   // 102400

__device__ __forceinline__ void gemm_body(
    const __half* __restrict__ A16, const __half* __restrict__ B16,
    const float* __restrict__ bias, float* __restrict__ OutF,
    __half* __restrict__ OutH, int do_softmax)
{
    extern __shared__ __align__(128) char sm[];
    uint32_t smb = smem_to_u32(sm);
    const int tid = threadIdx.x;
    const int m0 = blockIdx.y * BM, n0 = blockIdx.x * BN;

    const __half* a_g = A16 + (size_t)m0 * NC;
    const __half* b_g = B16 + (size_t)n0 * NC;

    auto issue = [&](int stage, int k0) {
        uint32_t sb = smb + stage * STG_BYTES;
        #pragma unroll
        for (int i = 0; i < 2; i++) {                 // A and B: 512 cp16 each
            int g = i * 256 + tid;
            int row = g >> 2, c = g & 3;
            uint32_t so = row * (SROW * 2) + c * 16;
            size_t  go = (size_t)row * NC + k0 + c * 8;
            cp16(sb + so,         a_g + go);
            cp16(sb + OFF_B + so, b_g + go);
        }
    };

    #pragma unroll
    for (int s = 0; s < STAGES - 1; s++) { issue(s, s * BK); cp_commit(); }

    const int wid = tid >> 5, lane = tid & 31;
    const int wm = wid & 3, wn = wid >> 2;            // warp tile: 32(M) x 64(N)

    float acc[2][8][4];
    #pragma unroll
    for (int a = 0; a < 2; a++)
        #pragma unroll
        for (int b = 0; b < 8; b++)
            #pragma unroll
            for (int c = 0; c < 4; c++) acc[a][b][c] = 0.f;

    const int a_row = wm * 32 + (lane & 7) + ((lane >> 3) & 1) * 8;   // + mt*16
    const int b_row = wn * 64 + (lane & 15);                           // + p*16
    const int colb  = (lane >> 4) * 16;                                // + ks*32

    for (int kt = 0; kt < NKT; kt++) {
        cp_wait<STAGES - 2>();
        __syncthreads();
        if (kt + STAGES - 1 < NKT) issue((kt + STAGES - 1) % STAGES, (kt + STAGES - 1) * BK);
        cp_commit();
        uint32_t sb = smb + (kt % STAGES) * STG_BYTES;
        #pragma unroll
        for (int ks = 0; ks < 2; ks++) {
            uint32_t ah[2][4];
            #pragma unroll
            for (int mt = 0; mt < 2; mt++)
                ldm_x4(sb + (a_row + mt * 16) * (SROW * 2) + ks * 32 + colb, ah[mt]);
            uint32_t bh[8][2];
            #pragma unroll
            for (int p = 0; p < 4; p++) {
                uint32_t t[4];
                ldm_x4(sb + OFF_B + (b_row + p * 16) * (SROW * 2) + ks * 32 + colb, t);
                bh[2*p][0] = t[0]; bh[2*p+1][0] = t[1]; bh[2*p][1] = t[2]; bh[2*p+1][1] = t[3];
            }
            #pragma unroll
            for (int mt = 0; mt < 2; mt++)
                #pragma unroll
                for (int nt = 0; nt < 8; nt++) mma_f16(acc[mt][nt], ah[mt], bh[nt]);
        }
    }

    // ---- Epilogue: bias (+softmax per 64-wide head) + store ----
    float2 bias2[8];
    const int cb = n0 + wn * 64 + (lane & 3) * 2;
    #pragma unroll
    for (int nt = 0; nt < 8; nt++)
        bias2[nt] = *reinterpret_cast<const float2*>(&bias[cb + nt * 8]);

    #pragma unroll
    for (int mt = 0; mt < 2; mt++) {
        float va[16], vb[16];
        #pragma unroll
        for (int nt = 0; nt < 8; nt++) {
            va[2*nt]   = acc[mt][nt][0] + bias2[nt].x;
            va[2*nt+1] = acc[mt][nt][1] + bias2[nt].y;
            vb[2*nt]   = acc[mt][nt][2] + bias2[nt].x;
            vb[2*nt+1] = acc[mt][nt][3] + bias2[nt].y;
        }
        if (do_softmax) { softmax16(va); softmax16(vb); }
        const int rowa = m0 + wm * 32 + mt * 16 + (lane >> 2);
        const int rowb = rowa + 8;
        if (OutH) {
            #pragma unroll
            for (int nt = 0; nt < 8; nt++) {
                *reinterpret_cast<__half2*>(&OutH[(size_t)rowa * NC + cb + nt * 8]) =
                    __floats2half2_rn(va[2*nt], va[2*nt+1]);
                *reinterpret_cast<__half2*>(&OutH[(size_t)rowb * NC + cb + nt * 8]) =
                    __floats2half2_rn(vb[2*nt], vb[2*nt+1]);
            }
        } else {
            #pragma unroll
            for (int nt = 0; nt < 8; nt++) {
                *reinterpret_cast<float2*>(&OutF[(size_t)rowa * NC + cb + nt * 8]) =
                    make_float2(va[2*nt], va[2*nt+1]);
                *reinterpret_cast<float2*>(&OutF[(size_t)rowb * NC + cb + nt * 8]) =
                    make_float2(vb[2*nt], vb[2*nt+1]);
            }
        }
    }
}

// K,V projections (softmax for K only)
__global__ __launch_bounds__(256, 2) void kv_gemm(
    const float* __restrict__ bk, const float* __restrict__ bv)
{
    if (blockIdx.z == 0) gemm_body(g_y16, g_wk, bk, nullptr, g_K, 1);
    else                 gemm_body(g_y16, g_wv, bv, nullptr, g_V, 0);
}

// Q projection (softmax)
__global__ __launch_bounds__(256, 2) void q_gemm(const float* __restrict__ bq)
{
    gemm_body(g_x16, g_wq, bq, nullptr, g_Q, 1);
}

__global__ __launch_bounds__(256, 2) void proj_gemm(
    const float* __restrict__ bp, float* __restrict__ out)
{
    gemm_body(g_a16, g_wp, bp, out, nullptr, 0);
}

// ---------------------------------------------------------------------------
// fp32 -> fp16 converts (merged launches)
// ---------------------------------------------------------------------------
__global__ __launch_bounds__(256) void convert_act(const float* __restrict__ x,
                                                   const float* __restrict__ y)
{
    const float* src = blockIdx.y ? y : x;
    __half* dh = blockIdx.y ? g_y16 : g_x16;
    int g = blockIdx.x * 256 + threadIdx.x;
    const float4* p = reinterpret_cast<const float4*>(src) + (size_t)g * 2;
    float4 a = p[0], b = p[1];
    alignas(16) __half h[8] = {
        __float2half_rn(a.x), __float2half_rn(a.y), __float2half_rn(a.z), __float2half_rn(a.w),
        __float2half_rn(b.x), __float2half_rn(b.y), __float2half_rn(b.z), __float2half_rn(b.w) };
    *reinterpret_cast<uint4*>(dh + (size_t)g * 8) = *reinterpret_cast<uint4*>(h);
}

__global__ __launch_bounds__(256) void convert_w(const float* __restrict__ wq,
                                                 const float* __restrict__ wk,
                                                 const float* __restrict__ wv,
                                                 const float* __restrict__ wp)
{
    const float* src; __half* dh;
    switch (blockIdx.y) {
        case 0: src = wq; dh = g_wq; break;
        case 1: src = wk; dh = g_wk; break;
        case 2: src = wv; dh = g_wv; break;
        default: src = wp; dh = g_wp; break;
    }
    int g = blockIdx.x * 256 + threadIdx.x;
    const float4* p = reinterpret_cast<const float4*>(src) + (size_t)g * 2;
    float4 a = p[0], b = p[1];
    alignas(16) __half h[8] = {
        __float2half_rn(a.x), __float2half_rn(a.y), __float2half_rn(a.z), __float2half_rn(a.w),
        __float2half_rn(b.x), __float2half_rn(b.y), __float2half_rn(b.z), __float2half_rn(b.w) };
    *reinterpret_cast<uint4*>(dh + (size_t)g * 8) = *reinterpret_cast<uint4*>(h);
}

// ---------------------------------------------------------------------------
// kv via HMMA: kv[d][e] = sum_n K[n,d]*V[n,e]; ksum[d] = sum_n K[n,d]
// grid (64 bh, KVSPL splits), 256 thr (8 warps as 4(d) x 2(e)).
// ---------------------------------------------------------------------------
#define KV_ROW 176                 // bytes per smem row (88 halfs)
#define KV_MAT (128*KV_ROW)        // 22528
#define KV_STG (2*KV_MAT)          // 45056 (K then V)
#define KV_SMEM (2*KV_STG)         // 90112
#define KV_TILES (NT/KVSPL/128)    // 8

__global__ __launch_bounds__(256, 1) void kv_hmma()
{
    extern __shared__ __align__(128) char sm[];
    uint32_t smb = smem_to_u32(sm);
    const int bh = blockIdx.x, split = blockIdx.y;
    const int tid = threadIdx.x, wid = tid >> 5, lane = tid & 31;
    const int wm = wid & 3, wn = wid >> 2;
    const int m0 = wm * 16, n0 = wn * 32;
    const int lr = lane & 7, lg = lane >> 3;

    const __half* Kp = g_K + (size_t)(bh / NH) * NT * NC + (bh % NH) * ND;
    const __half* Vp = g_V + (size_t)(bh / NH) * NT * NC + (bh % NH) * ND;
    const int tokbase = split * (NT / KVSPL);

    auto issue = [&](int stage, int tile) {
        uint32_t sb = smb + stage * KV_STG;
        int t0 = tokbase + tile * 128;
        #pragma unroll
        for (int i = 0; i < 4; i++) {
            int slot = i * 256 + tid;
            int row = slot >> 3, c = slot & 7;
            cp16(sb + row * KV_ROW + c * 16,          Kp + (size_t)(t0 + row) * NC + c * 8);
            cp16(sb + KV_MAT + row * KV_ROW + c * 16, Vp + (size_t)(t0 + row) * NC + c * 8);
        }
        int row = tid >> 1, which = tid & 1;
        uint4 padv = which ? make_uint4(0u, 0u, 0u, 0u)
                           : make_uint4(0x00003C00u, 0u, 0u, 0u);
        *reinterpret_cast<uint4*>(sm + stage * KV_STG + KV_MAT + row * KV_ROW + 128 + which * 16) = padv;
    };

    float acc[4][4] = {};
    float accS[4]   = {};

    issue(0, 0); cp_commit();

    for (int tile = 0; tile < KV_TILES; tile++) {
        if (tile + 1 < KV_TILES) { issue((tile + 1) & 1, tile + 1); cp_commit(); cp_wait<1>(); }
        else cp_wait<0>();
        __syncthreads();
        uint32_t kb = smb + (tile & 1) * KV_STG;
        uint32_t vb = kb + KV_MAT;
        #pragma unroll
        for (int s = 0; s < 8; s++) {
            int ts = s * 16;
            uint32_t a[4];
            ldm_x4_t(kb + (ts + lr + (lg >> 1) * 8) * KV_ROW + (m0 + (lg & 1) * 8) * 2, a);
            #pragma unroll
            for (int eg = 0; eg < 2; eg++) {
                uint32_t t[4];
                ldm_x4_t(vb + (ts + lr + (lg & 1) * 8) * KV_ROW + (n0 + eg * 16 + (lg >> 1) * 8) * 2, t);
                mma_f16(acc[eg * 2 + 0], a, t + 0);
                mma_f16(acc[eg * 2 + 1], a, t + 2);
            }
            if (wn == 1) {
                uint32_t t[4];
                ldm_x4_t(vb + (ts + lr + (lg & 1) * 8) * KV_ROW + (64 + (lg >> 1) * 8) * 2, t);
                mma_f16(accS, a, t + 0);
            }
        }
        __syncthreads();
    }

    float* kvout = g_KV2 + ((size_t)split * 64 + bh) * 4096;
    const int r0 = m0 + (lane >> 2), c0 = (lane & 3) * 2;
    #pragma unroll
    for (int j = 0; j < 4; j++) {
        *reinterpret_cast<float2*>(&kvout[r0 * 64 + n0 + j * 8 + c0]) =
            make_float2(acc[j][0], acc[j][1]);
        *reinterpret_cast<float2*>(&kvout[(r0 + 8) * 64 + n0 + j * 8 + c0]) =
            make_float2(acc[j][2], acc[j][3]);
    }
    if (wn == 1 && (lane & 3) == 0) {
        float* ksout = g_KS2 + ((size_t)split * 64 + bh) * 64;
        ksout[m0 + (lane >> 2)]     = accS[0];
        ksout[m0 + 8 + (lane >> 2)] = accS[2];
    }
}

// ---------------------------------------------------------------------------
// kv_reduce: sum KVSPL splits -> fp16 kv^T tile [80 rows x 72 halfs] per bh:
//   rows 0-63: kvT[e][d] = kv[d][e]; row 64: ksum[d]; rows 65-71: zero.
// ---------------------------------------------------------------------------
__global__ __launch_bounds__(256) void kv_reduce()
{
    const int bh = blockIdx.x, tid = threadIdx.x;
    __half* dst = g_KVT + (size_t)bh * 5760;
    #pragma unroll
    for (int i = 0; i < 16; i++) {
        int idx = i * 256 + tid;
        int d = idx >> 6, e = idx & 63;
        float s = 0.f;
        #pragma unroll
        for (int sp = 0; sp < KVSPL; sp++)
            s += g_KV2[((size_t)sp * 64 + bh) * 4096 + idx];
        dst[e * 72 + d] = __float2half_rn(s);
    }
    if (tid < 64) {
        float s = 0.f;
        #pragma unroll
        for (int sp = 0; sp < KVSPL; sp++) s += g_KS2[(sp * 64 + bh) * 64 + tid];
        dst[64 * 72 + tid] = __float2half_rn(s);
    }
    // zero row 64 cols 64-71 and rows 65-71
    for (int j = tid; j < 512; j += 256) dst[64 * 72 + 64 + j] = __float2half_rn(0.f);
}

// ---------------------------------------------------------------------------
// attn via HMMA: os[t,e] = sum_d q[t,d]*kvT[e,d]; ds[t] from ksum row (n=64).
// out[t,e] = q[t,e] + os/ds -> fp16 for proj GEMM.
// ---------------------------------------------------------------------------
#define AT_ROW 144   // 72 halfs per smem row

__global__ __launch_bounds__(256) void attn_hmma()
{
    __shared__ __align__(16) char sq[128 * AT_ROW];  // Q tile: 128 tok x 64 d
    __shared__ __align__(16) char sb[80 * AT_ROW];   // kvT + ksum tile
    const int bh = blockIdx.y, b = bh / NH, h = bh % NH;
    const int t0 = blockIdx.x * 128;
    const int tid = threadIdx.x, wid = tid >> 5, lane = tid & 31;
    uint32_t sqb = smem_to_u32(sq), sbb = smem_to_u32(sb);

    const __half* Qp = g_Q + ((size_t)b * NT + t0) * NC + h * ND;
    #pragma unroll
    for (int i = 0; i < 4; i++) {                     // 1024 cp16
        int slot = i * 256 + tid;
        int row = slot >> 3, c = slot & 7;
        cp16(sqb + row * AT_ROW + c * 16, Qp + (size_t)row * NC + c * 8);
    }
    const __half* Bp = g_KVT + (size_t)bh * 5760;     // 720 cp16
    for (int s = tid; s < 720; s += 256) cp16(sbb + s * 16, Bp + s * 8);
    cp_commit(); cp_wait<0>();
    __syncthreads();

    float acc[9][4] = {};                              // 8 n-tiles + ksum tile
    const int a_row = wid * 16 + (lane & 7) + ((lane >> 3) & 1) * 8;
    const int b_row = lane & 15;
    const int colb  = (lane >> 4) * 16;

    #pragma unroll
    for (int ks = 0; ks < 4; ks++) {
        uint32_t a[4];
        ldm_x4(sqb + a_row * AT_ROW + ks * 32 + colb, a);
        #pragma unroll
        for (int p = 0; p < 5; p++) {
            uint32_t t[4];
            ldm_x4(sbb + (b_row + p * 16) * AT_ROW + ks * 32 + colb, t);
            uint32_t f0[2] = { t[0], t[2] };
            mma_f16(acc[2 * p], a, f0);
            if (p < 4) {
                uint32_t f1[2] = { t[1], t[3] };
                mma_f16(acc[2 * p + 1], a, f1);
            }
        }
    }

    float ds0 = __shfl_sync(0xffffffffu, acc[8][0], lane & ~3);
    float ds1 = __shfl_sync(0xffffffffu, acc[8][2], lane & ~3);
    ds0 = 1.f / ds0; ds1 = 1.f / ds1;

    const int r = wid * 16 + (lane >> 2);
    const int cb = (lane & 3) * 2;
    __half* outp = g_a16 + ((size_t)b * NT + t0) * NC + h * ND;
    #pragma unroll
    for (int nt = 0; nt < 8; nt++) {
        int e = nt * 8 + cb;
        __half2 q0 = *reinterpret_cast<const __half2*>(sq + r * AT_ROW + e * 2);
        __half2 q1 = *reinterpret_cast<const __half2*>(sq + (r + 8) * AT_ROW + e * 2);
        float2 qf0 = __half22float2(q0), qf1 = __half22float2(q1);
        *reinterpret_cast<__half2*>(outp + (size_t)r * NC + e) =
            __floats2half2_rn(qf0.x + acc[nt][0] * ds0, qf0.y + acc[nt][1] * ds0);
        *reinterpret_cast<__half2*>(outp + (size_t)(r + 8) * NC + e) =
            __floats2half2_rn(qf1.x + acc[nt][2] * ds1, qf1.y + acc[nt][3] * ds1);
    }
}

// ---------------------------------------------------------------------------
extern "C" void kernel_launch(void* const* d_in, const int* in_sizes, int n_in,
                              void* d_out, int out_size)
{
    const float* x  = (const float*)d_in[0];
    const float* y  = (const float*)d_in[1];
    const float* Wq = (const float*)d_in[2];
    const float* bq = (const float*)d_in[3];
    const float* Wk = (const float*)d_in[4];
    const float* bk = (const float*)d_in[5];
    const float* Wv = (const float*)d_in[6];
    const float* bv = (const float*)d_in[7];
    const float* Wp = (const float*)d_in[8];
    const float* bp = (const float*)d_in[9];
    float* out = (float*)d_out;
    (void)in_sizes; (void)n_in; (void)out_size;

    // Host-side objects created once (first call is the uncaptured correctness
    // run); no device memory involved. Side stream is non-blocking so it can
    // truly overlap with the main stream inside the captured graph.
    static cudaStream_t s2 = nullptr;
    static cudaEvent_t ev_fork = nullptr, ev_join = nullptr;
    if (s2 == nullptr) {
        cudaStreamCreateWithFlags(&s2, cudaStreamNonBlocking);
        cudaEventCreateWithFlags(&ev_fork, cudaEventDisableTiming);
        cudaEventCreateWithFlags(&ev_join, cudaEventDisableTiming);
    }

    cudaFuncSetAttribute(kv_gemm,   cudaFuncAttributeMaxDynamicSharedMemorySize, GSMEM);
    cudaFuncSetAttribute(q_gemm,    cudaFuncAttributeMaxDynamicSharedMemorySize, GSMEM);
    cudaFuncSetAttribute(proj_gemm, cudaFuncAttributeMaxDynamicSharedMemorySize, GSMEM);
    cudaFuncSetAttribute(kv_hmma,   cudaFuncAttributeMaxDynamicSharedMemorySize, KV_SMEM);

    // 1. fp32 -> fp16 (merged)
    convert_act<<<dim3(NM * NC / 8 / 256, 2), 256>>>(x, y);
    convert_w<<<dim3(NC * NC / 8 / 256, 4), 256>>>(Wq, Wk, Wv, Wp);

    // 2. K/V projections (softmax fused for K) -> fp16
    kv_gemm<<<dim3(NC / BN, NM / BM, 2), 256, GSMEM>>>(bk, bv);

    // Fork: Q projection on side stream, overlapping kv_hmma + kv_reduce.
    cudaEventRecord(ev_fork, 0);
    cudaStreamWaitEvent(s2, ev_fork, 0);
    q_gemm<<<dim3(NC / BN, NM / BM, 1), 256, GSMEM, s2>>>(bq);
    cudaEventRecord(ev_join, s2);

    // 3. kv = K^T V (+ksum) on tensor cores, 4-way T split, then fp16 reduce
    kv_hmma<<<dim3(NB * NH, KVSPL), 256, KV_SMEM>>>();
    kv_reduce<<<NB * NH, 256>>>();

    // Join: attn needs both Q (side stream) and kvT (main stream).
    cudaStreamWaitEvent(0, ev_join, 0);

    // 4. linear-attention combine on tensor cores -> fp16 for proj GEMM
    attn_hmma<<<dim3(NT / 128, NB * NH), 256>>>();

    // 5. output projection -> d_out (fp32)
    proj_gemm<<<dim3(NC / BN, NM / BM, 1), 256, GSMEM>>>(bp, out);
}